// round 14
// baseline (speedup 1.0000x reference)
#include <cuda_runtime.h>

#define IMG 4096
#define OT   64                 // output tile edge
#define HALO 7
#define IT   (OT + 2*HALO)      // 78 input tile edge
#define SR   (IT + 1)           // 79 SAT rows/cols (zero border at row/col 0)
#define STRIDE 85               // gcd(85,32)=1 -> conflict-free everywhere

__global__ __launch_bounds__(256, 5) void meanconv_satstream_kernel(
    const float* __restrict__ x,
    const float* __restrict__ mask,
    float* __restrict__ out)
{
    __shared__ float T[SR * STRIDE];   // 79*85*4 = 26.9 KB

    const int t   = threadIdx.x;
    const int gx0 = blockIdx.x * OT;
    const int gy0 = blockIdx.y * OT;

    // Zero SAT border (row 0 and col 0)
    for (int i = t; i < SR; i += 256) { T[i] = 0.0f; T[i * STRIDE] = 0.0f; }

    // Load 78x78 clamped input tile (clamping == replicate padding)
    for (int idx = t; idx < IT * IT; idx += 256) {
        int r = idx / IT;
        int c = idx - r * IT;
        int gy = gy0 - HALO + r; gy = min(max(gy, 0), IMG - 1);
        int gx = gx0 - HALO + c; gx = min(max(gx, 0), IMG - 1);
        T[(r + 1) * STRIDE + (c + 1)] = __ldg(&x[gy * IMG + gx]);
    }
    __syncthreads();

    // Column prefix sums (thread per column)
    if (t < IT) {
        const int c = t + 1;
        float acc = 0.0f;
        #pragma unroll 6
        for (int r = 1; r < SR; r++) {
            acc += T[r * STRIDE + c];
            T[r * STRIDE + c] = acc;
        }
    }
    __syncthreads();

    // Row prefix sums (thread per row; stride 85 -> conflict-free)
    if (t < IT) {
        float* Trow = &T[(t + 1) * STRIDE];
        float acc = 0.0f;
        #pragma unroll 6
        for (int c = 1; c < SR; c++) {
            acc += Trow[c];
            Trow[c] = acc;
        }
    }
    __syncthreads();

    // ---- Query: per-scale corner streaming, interleaved load/consume ----
    // d[rl] = right-col - left-col SAT difference for scale p at row rl.
    // Output j uses d[j] (top) and d[j+L] (bottom), L = 2p+1. Consuming
    // acc[rl-L] as soon as d[rl] lands keeps only L+1 d-values live (<=16),
    // so the whole query fits a 51-reg cap (5 CTAs/SM, 40 warps).
    const int tx = t & (OT - 1);
    const int y0 = (t >> 6) * 16;   // 0,16,32,48

    const float W[8] = { 0.0f,
        1.0f/63.0f, 1.0f/175.0f, 1.0f/343.0f, 1.0f/567.0f,
        1.0f/847.0f, 1.0f/1183.0f, 1.0f/1575.0f };

    float acc[16];
    #pragma unroll
    for (int j = 0; j < 16; j++) acc[j] = 0.0f;

    #pragma unroll
    for (int p = 1; p <= 7; p++) {
        const int L  = 2 * p + 1;
        const int NR = 16 + L;                     // distinct rows this scale
        const float* Tl = &T[(y0 + HALO - p) * STRIDE + tx + HALO - p];      // left  col
        const float* Tr = &T[(y0 + HALO - p) * STRIDE + tx + HALO + 1 + p];  // right col
        const float wp = W[p];

        float d[31];                               // compile-time indexed; live window <= L+1
        #pragma unroll
        for (int rl = 0; rl < NR; rl++) {
            d[rl] = Tr[rl * STRIDE] - Tl[rl * STRIDE];
            if (rl >= L)
                acc[rl - L] = fmaf(wp, d[rl] - d[rl - L], acc[rl - L]);
        }
    }

    // ---- Masked store (coalesced) ----
    #pragma unroll
    for (int j = 0; j < 16; j++) {
        const int g = (gy0 + y0 + j) * IMG + (gx0 + tx);
        out[g] = acc[j] * __ldg(&mask[g]);
    }
}

extern "C" void kernel_launch(void* const* d_in, const int* in_sizes, int n_in,
                              void* d_out, int out_size)
{
    (void)n_in; (void)in_sizes; (void)out_size;
    const float* x    = (const float*)d_in[0];
    const float* mask = (const float*)d_in[1];
    float* out        = (float*)d_out;

    dim3 grid(IMG / OT, IMG / OT);   // 64 x 64 tiles
    meanconv_satstream_kernel<<<grid, 256>>>(x, mask, out);
}

// round 15
// speedup vs baseline: 1.1616x; 1.1616x over previous
#include <cuda_runtime.h>

#define IMG 4096
#define OT   64                 // output tile edge
#define HALO 7
#define IT   (OT + 2*HALO)      // 78 input tile edge
#define SR   (IT + 1)           // 79 SAT rows/cols (zero border at row/col 0)
#define STRIDE 85               // gcd(85,32)=1 -> conflict-free everywhere
#define KY   32                 // y-outputs per thread (2 groups x 32 = 64 rows)

__global__ __launch_bounds__(128, 7) void meanconv_sat32_kernel(
    const float* __restrict__ x,
    const float* __restrict__ mask,
    float* __restrict__ out)
{
    __shared__ float T[SR * STRIDE];   // 79*85*4 = 26.9 KB

    const int t   = threadIdx.x;       // 0..127
    const int gx0 = blockIdx.x * OT;
    const int gy0 = blockIdx.y * OT;

    // Zero SAT border (row 0 and col 0)
    for (int i = t; i < SR; i += 128) { T[i] = 0.0f; T[i * STRIDE] = 0.0f; }

    // Load 78x78 clamped input tile (clamping == replicate padding)
    for (int idx = t; idx < IT * IT; idx += 128) {
        int r = idx / IT;
        int c = idx - r * IT;
        int gy = gy0 - HALO + r; gy = min(max(gy, 0), IMG - 1);
        int gx = gx0 - HALO + c; gx = min(max(gx, 0), IMG - 1);
        T[(r + 1) * STRIDE + (c + 1)] = __ldg(&x[gy * IMG + gx]);
    }
    __syncthreads();

    // Column prefix sums (thread per column)
    if (t < IT) {
        const int c = t + 1;
        float acc = 0.0f;
        #pragma unroll 6
        for (int r = 1; r < SR; r++) {
            acc += T[r * STRIDE + c];
            T[r * STRIDE + c] = acc;
        }
    }
    __syncthreads();

    // Row prefix sums (thread per row; stride 85 -> conflict-free)
    if (t < IT) {
        float* Trow = &T[(t + 1) * STRIDE];
        float acc = 0.0f;
        #pragma unroll 6
        for (int c = 1; c < SR; c++) {
            acc += Trow[c];
            Trow[c] = acc;
        }
    }
    __syncthreads();

    // ---- Query: per-scale corner streaming over 32 rows per thread ----
    // d[rl] = right - left SAT corner difference for scale p at local row rl.
    // Output j consumes d[j] (top) and d[j+L] (bottom), L = 2p+1; consuming
    // acc[rl-L] as soon as d[rl] lands bounds the live d-window to L+1 <= 16.
    const int tx = t & (OT - 1);
    const int y0 = (t >> 6) * KY;   // 0 or 32

    const float W[8] = { 0.0f,
        1.0f/63.0f, 1.0f/175.0f, 1.0f/343.0f, 1.0f/567.0f,
        1.0f/847.0f, 1.0f/1183.0f, 1.0f/1575.0f };

    float acc[KY];
    #pragma unroll
    for (int j = 0; j < KY; j++) acc[j] = 0.0f;

    #pragma unroll
    for (int p = 1; p <= 7; p++) {
        const int L  = 2 * p + 1;
        const int NR = KY + L;                     // distinct rows this scale (35..47)
        const float* Tl = &T[(y0 + HALO - p) * STRIDE + tx + HALO - p];      // left  col
        const float* Tr = &T[(y0 + HALO - p) * STRIDE + tx + HALO + 1 + p];  // right col
        const float wp = W[p];

        float d[KY + 15];                          // compile-time indexed -> regs
        #pragma unroll
        for (int rl = 0; rl < NR; rl++) {
            d[rl] = Tr[rl * STRIDE] - Tl[rl * STRIDE];
            if (rl >= L)
                acc[rl - L] = fmaf(wp, d[rl] - d[rl - L], acc[rl - L]);
        }
    }

    // ---- Masked store (coalesced) ----
    #pragma unroll
    for (int j = 0; j < KY; j++) {
        const int g = (gy0 + y0 + j) * IMG + (gx0 + tx);
        out[g] = acc[j] * __ldg(&mask[g]);
    }
}

extern "C" void kernel_launch(void* const* d_in, const int* in_sizes, int n_in,
                              void* d_out, int out_size)
{
    (void)n_in; (void)in_sizes; (void)out_size;
    const float* x    = (const float*)d_in[0];
    const float* mask = (const float*)d_in[1];
    float* out        = (float*)d_out;

    dim3 grid(IMG / OT, IMG / OT);   // 64 x 64 tiles
    meanconv_sat32_kernel<<<grid, 128>>>(x, mask, out);
}

// round 17
// speedup vs baseline: 1.1704x; 1.0076x over previous
#include <cuda_runtime.h>

#define IMG 4096
#define OT   64                 // output tile edge
#define HALO 7
#define IT   (OT + 2*HALO)      // 78 input tile edge
#define SR   (IT + 1)           // 79 SAT rows/cols (zero border at row/col 0)
#define STRIDE 85               // gcd(85,32)=1 -> conflict-free everywhere
#define KY   32                 // y-outputs per thread (2 groups x 32 = 64 rows)

__global__ __launch_bounds__(128, 7) void meanconv_sat32f2_kernel(
    const float* __restrict__ x,
    const float* __restrict__ mask,
    float* __restrict__ out)
{
    __shared__ float T[SR * STRIDE];   // 79*85*4 = 26.9 KB

    const int t   = threadIdx.x;       // 0..127
    const int gx0 = blockIdx.x * OT;
    const int gy0 = blockIdx.y * OT;

    // Zero SAT border (row 0 and col 0)
    for (int i = t; i < SR; i += 128) { T[i] = 0.0f; T[i * STRIDE] = 0.0f; }

    // ---- Load clamped raw tile; interior tiles take a vectorized fast path ----
    const bool interior = (blockIdx.x >= 1) & (blockIdx.x <= 62) &
                          (blockIdx.y >= 1) & (blockIdx.y <= 62);
    if (interior) {
        // Window rows gy0-7..gy0+70, cols gx0-8..gx0+71 fully in-bounds; gx0-8
        // is 16B-aligned so float4 loads are legal. Element c' of a row maps to
        // smem col c' (raw col c = c'-1 at col c+1). c'=0 (the gx0-8 element)
        // is NOT stored: col 0 keeps the SAT zero border. Junk at col 79 is
        // never read (queries use cols <= 78, prefixes touch 1..78 only).
        const float* src = x + (gy0 - HALO) * IMG + (gx0 - 8);
        for (int idx = t; idx < IT * 20; idx += 128) {
            int r  = idx / 20;
            int c4 = idx - r * 20;
            float4 v = __ldg((const float4*)(src + r * IMG) + c4);
            float* dst = &T[(r + 1) * STRIDE + c4 * 4];
            if (c4 != 0) dst[0] = v.x;        // col 0 stays zero (SAT border)
            dst[1] = v.y; dst[2] = v.z; dst[3] = v.w;
        }
    } else {
        for (int idx = t; idx < IT * IT; idx += 128) {
            int r = idx / IT;
            int c = idx - r * IT;
            int gy = gy0 - HALO + r; gy = min(max(gy, 0), IMG - 1);
            int gx = gx0 - HALO + c; gx = min(max(gx, 0), IMG - 1);
            T[(r + 1) * STRIDE + (c + 1)] = __ldg(&x[gy * IMG + gx]);
        }
    }
    __syncthreads();

    // Column prefix sums (thread per column)
    if (t < IT) {
        const int c = t + 1;
        float acc = 0.0f;
        #pragma unroll 6
        for (int r = 1; r < SR; r++) {
            acc += T[r * STRIDE + c];
            T[r * STRIDE + c] = acc;
        }
    }
    __syncthreads();

    // Row prefix sums (thread per row; stride 85 -> conflict-free)
    if (t < IT) {
        float* Trow = &T[(t + 1) * STRIDE];
        float acc = 0.0f;
        #pragma unroll 6
        for (int c = 1; c < SR; c++) {
            acc += Trow[c];
            Trow[c] = acc;
        }
    }
    __syncthreads();

    // ---- Query: per-scale corner streaming over 32 rows per thread ----
    // d[rl] = right - left SAT corner difference for scale p at local row rl.
    // Output j consumes d[j] (top) and d[j+L] (bottom), L = 2p+1; consuming
    // acc[rl-L] as soon as d[rl] lands bounds the live d-window to L+1 <= 16.
    const int tx = t & (OT - 1);
    const int y0 = (t >> 6) * KY;   // 0 or 32

    const float W[8] = { 0.0f,
        1.0f/63.0f, 1.0f/175.0f, 1.0f/343.0f, 1.0f/567.0f,
        1.0f/847.0f, 1.0f/1183.0f, 1.0f/1575.0f };

    float acc[KY];
    #pragma unroll
    for (int j = 0; j < KY; j++) acc[j] = 0.0f;

    #pragma unroll
    for (int p = 1; p <= 7; p++) {
        const int L  = 2 * p + 1;
        const int NR = KY + L;                     // distinct rows this scale (35..47)
        const float* Tl = &T[(y0 + HALO - p) * STRIDE + tx + HALO - p];      // left  col
        const float* Tr = &T[(y0 + HALO - p) * STRIDE + tx + HALO + 1 + p];  // right col
        const float wp = W[p];

        float d[KY + 15];                          // compile-time indexed -> regs
        #pragma unroll
        for (int rl = 0; rl < NR; rl++) {
            d[rl] = Tr[rl * STRIDE] - Tl[rl * STRIDE];
            if (rl >= L)
                acc[rl - L] = fmaf(wp, d[rl] - d[rl - L], acc[rl - L]);
        }
    }

    // ---- Masked store (coalesced) ----
    #pragma unroll
    for (int j = 0; j < KY; j++) {
        const int g = (gy0 + y0 + j) * IMG + (gx0 + tx);
        out[g] = acc[j] * __ldg(&mask[g]);
    }
}

extern "C" void kernel_launch(void* const* d_in, const int* in_sizes, int n_in,
                              void* d_out, int out_size)
{
    (void)n_in; (void)in_sizes; (void)out_size;
    const float* x    = (const float*)d_in[0];
    const float* mask = (const float*)d_in[1];
    float* out        = (float*)d_out;

    dim3 grid(IMG / OT, IMG / OT);   // 64 x 64 tiles
    meanconv_sat32f2_kernel<<<grid, 128>>>(x, mask, out);
}